// round 5
// baseline (speedup 1.0000x reference)
#include <cuda_runtime.h>

#define NMAX 100000
#define EMAX 3200000
#define FIN 128
#define HID 24
#define NC  16
#define SCAN_B 1024

// Scratch (static __device__ arrays — no allocation). 16B-aligned for float4.
__device__ int   g_cnt[NMAX];
__device__ float g_dinv[NMAX];
__device__ int   g_ptr[NMAX + 1];
__device__ int   g_cur[NMAX];
__device__ int   g_off[128];
__device__ int   g_bsum[128];
__device__ int   g_csr[EMAX];
__device__ __align__(16) float g_h1[NMAX * HID];
__device__ __align__(16) float g_a1[NMAX * HID];
__device__ __align__(16) float g_h2[NMAX * NC];

// ---- 0. zero counts -------------------------------------------------------
__global__ void k_zero(int n) {
    int i = blockIdx.x * blockDim.x + threadIdx.x;
    if (i < n) g_cnt[i] = 0;
}

// ---- 1. count edges per dst (edge_index is int32!) -----------------------
__global__ void k_count(const int* __restrict__ er, int E, int n) {
    int e = blockIdx.x * blockDim.x + threadIdx.x;
    if (e < E) {
        int r = er[e];
        if ((unsigned)r < (unsigned)n) atomicAdd(&g_cnt[r], 1);
    }
}

// ---- 2a. per-block inclusive scan ----------------------------------------
__global__ void k_scanA(int n) {
    __shared__ int s[SCAN_B];
    int tid = threadIdx.x;
    int gi = blockIdx.x * SCAN_B + tid;
    int v = (gi < n) ? g_cnt[gi] : 0;
    s[tid] = v;
    __syncthreads();
    #pragma unroll
    for (int d = 1; d < SCAN_B; d <<= 1) {
        int t = (tid >= d) ? s[tid - d] : 0;
        __syncthreads();
        s[tid] += t;
        __syncthreads();
    }
    if (gi < n) g_ptr[gi + 1] = s[tid];
    if (tid == SCAN_B - 1) g_bsum[blockIdx.x] = s[tid];
}

// ---- 2b. serial scan of block totals (<=98) ------------------------------
__global__ void k_scanB(int nb) {
    int run = 0;
    for (int b = 0; b < nb; b++) { g_off[b] = run; run += g_bsum[b]; }
}

// ---- 2c. add offsets; cursors + dinv -------------------------------------
__global__ void k_scanC(int n) {
    int i = blockIdx.x * blockDim.x + threadIdx.x;
    if (i >= n) return;
    int off = g_off[i / SCAN_B];
    int inc = g_ptr[i + 1] + off;
    g_ptr[i + 1] = inc;
    g_cur[i] = inc - g_cnt[i];
    g_dinv[i] = rsqrtf((float)g_cnt[i] + 1.0f);
    if (i == 0) g_ptr[0] = 0;
}

// ---- 3. scatter cols into CSR --------------------------------------------
__global__ void k_scatter(const int* __restrict__ er,
                          const int* __restrict__ ec, int E, int n) {
    int e = blockIdx.x * blockDim.x + threadIdx.x;
    if (e >= E) return;
    int r = er[e];
    int c = ec[e];
    if ((unsigned)r < (unsigned)n && (unsigned)c < (unsigned)n) {
        int pos = atomicAdd(&g_cur[r], 1);
        g_csr[pos] = c;
    }
}

// ---- 4. GEMM1: h1 = x @ W1 -----------------------------------------------
__global__ void k_gemm1(const float* __restrict__ x, const float* __restrict__ W1, int n) {
    __shared__ float sx[64 * 129];
    __shared__ float sw[FIN * HID];
    int tid = threadIdx.x;
    int rowBase = blockIdx.x * 64;

    for (int i = tid; i < FIN * HID; i += 256) sw[i] = W1[i];
    for (int i = tid; i < 64 * FIN; i += 256) {
        int r = i >> 7, k = i & 127;
        int gr = rowBase + r;
        sx[r * 129 + k] = (gr < n) ? x[(size_t)gr * FIN + k] : 0.0f;
    }
    __syncthreads();

    int r   = tid & 63;
    int grp = tid >> 6;
    int j0  = grp * 6;
    float acc[6] = {0.f, 0.f, 0.f, 0.f, 0.f, 0.f};
    #pragma unroll 4
    for (int k = 0; k < FIN; k++) {
        float xv = sx[r * 129 + k];
        #pragma unroll
        for (int c = 0; c < 6; c++) acc[c] += xv * sw[k * HID + j0 + c];
    }
    __syncthreads();

    float* so = sx;  // reuse: 64 x 25
    #pragma unroll
    for (int c = 0; c < 6; c++) so[r * 25 + j0 + c] = acc[c];
    __syncthreads();

    for (int i = tid; i < 64 * HID; i += 256) {
        int rr = i / HID, j = i - rr * HID;
        int gr = rowBase + rr;
        if (gr < n) g_h1[(size_t)gr * HID + j] = so[rr * 25 + j];
    }
}

// ---- 5. Aggregation layer 1 (CSR gather, no atomics) ---------------------
// 8 threads/node, 6 active float4 lanes. Subgroup-local shfl masks.
__global__ void k_agg1(int n) {
    int t = blockIdx.x * blockDim.x + threadIdx.x;
    int node = t >> 3;
    bool nvalid = node < n;
    int nc = nvalid ? node : 0;
    int lane = threadIdx.x & 31;
    unsigned gmask = 0xffu << (lane & ~7);     // this 8-thread subgroup
    int sub = t & 7;
    bool active = nvalid && sub < 6;

    int start = nvalid ? g_ptr[nc]     : 0;
    int end   = nvalid ? g_ptr[nc + 1] : 0;
    float dr  = g_dinv[nc];

    float4 acc = make_float4(0.f, 0.f, 0.f, 0.f);
    if (active) {
        float4 v = *(const float4*)(g_h1 + (size_t)nc * HID + sub * 4);
        acc.x = dr * v.x; acc.y = dr * v.y; acc.z = dr * v.z; acc.w = dr * v.w;
    }

    for (int j0 = start; j0 < end; j0 += 8) {
        int jj = j0 + sub;
        int cc = (jj < end) ? __ldg(g_csr + jj) : -1;
        float dv = (cc >= 0) ? g_dinv[cc] : 0.0f;
        #pragma unroll
        for (int k = 0; k < 8; k++) {
            int   ck  = __shfl_sync(gmask, cc, k, 8);
            float dvk = __shfl_sync(gmask, dv, k, 8);
            if (ck >= 0 && active) {
                float4 v = *(const float4*)(g_h1 + (size_t)ck * HID + sub * 4);
                acc.x += dvk * v.x; acc.y += dvk * v.y;
                acc.z += dvk * v.z; acc.w += dvk * v.w;
            }
        }
    }
    if (active) {
        float4 o = make_float4(dr * acc.x, dr * acc.y, dr * acc.z, dr * acc.w);
        *(float4*)(g_a1 + (size_t)nc * HID + sub * 4) = o;
    }
}

// ---- 6. GEMM2: h2 = relu(a1 + b1) @ W2 -----------------------------------
__global__ void k_gemm2(const float* __restrict__ W2, const float* __restrict__ b1, int n) {
    __shared__ float sa[256 * 25];
    __shared__ float sw[HID * NC];
    int tid = threadIdx.x;
    int rowBase = blockIdx.x * 256;

    for (int i = tid; i < HID * NC; i += 256) sw[i] = W2[i];
    for (int i = tid; i < 256 * HID; i += 256) {
        int r = i / HID, k = i - r * HID;
        int gr = rowBase + r;
        float v = (gr < n) ? g_a1[(size_t)gr * HID + k] : 0.0f;
        sa[r * 25 + k] = fmaxf(v + b1[k], 0.0f);
    }
    __syncthreads();

    int r = tid;
    float acc[NC];
    #pragma unroll
    for (int j = 0; j < NC; j++) acc[j] = 0.0f;
    #pragma unroll
    for (int k = 0; k < HID; k++) {
        float xv = sa[r * 25 + k];
        #pragma unroll
        for (int j = 0; j < NC; j++) acc[j] += xv * sw[k * NC + j];
    }
    __syncthreads();

    float* so = sa;  // reuse: 256 x 17
    #pragma unroll
    for (int j = 0; j < NC; j++) so[r * 17 + j] = acc[j];
    __syncthreads();

    for (int i = tid; i < 256 * NC; i += 256) {
        int rr = i >> 4, j = i & 15;
        int gr = rowBase + rr;
        if (gr < n) g_h2[(size_t)gr * NC + j] = so[rr * 17 + j];
    }
}

// ---- 7. Aggregation layer 2 + bias + log_softmax fused -------------------
// 4 threads/node, each owns a float4 of the 16 output cols.
__global__ void k_agg2_lsm(const float* __restrict__ b2, float* __restrict__ out, int n) {
    int t = blockIdx.x * blockDim.x + threadIdx.x;
    int node = t >> 2;
    bool nvalid = node < n;
    int ncl = nvalid ? node : 0;
    int lane = threadIdx.x & 31;
    unsigned gmask = 0xfu << (lane & ~3);      // this 4-thread subgroup
    int sub = t & 3;

    int start = nvalid ? g_ptr[ncl]     : 0;
    int end   = nvalid ? g_ptr[ncl + 1] : 0;
    float dr  = g_dinv[ncl];

    float4 v0 = *(const float4*)(g_h2 + (size_t)ncl * NC + sub * 4);
    float4 acc = make_float4(dr * v0.x, dr * v0.y, dr * v0.z, dr * v0.w);

    for (int j0 = start; j0 < end; j0 += 4) {
        int jj = j0 + sub;
        int cc = (jj < end) ? __ldg(g_csr + jj) : -1;
        float dv = (cc >= 0) ? g_dinv[cc] : 0.0f;
        #pragma unroll
        for (int k = 0; k < 4; k++) {
            int   ck  = __shfl_sync(gmask, cc, k, 4);
            float dvk = __shfl_sync(gmask, dv, k, 4);
            if (ck >= 0) {
                float4 v = *(const float4*)(g_h2 + (size_t)ck * NC + sub * 4);
                acc.x += dvk * v.x; acc.y += dvk * v.y;
                acc.z += dvk * v.z; acc.w += dvk * v.w;
            }
        }
    }

    float4 bb = *(const float4*)(b2 + sub * 4);
    float4 o;
    o.x = dr * acc.x + bb.x; o.y = dr * acc.y + bb.y;
    o.z = dr * acc.z + bb.z; o.w = dr * acc.w + bb.w;

    float m = fmaxf(fmaxf(o.x, o.y), fmaxf(o.z, o.w));
    m = fmaxf(m, __shfl_xor_sync(gmask, m, 1, 4));
    m = fmaxf(m, __shfl_xor_sync(gmask, m, 2, 4));
    float s = expf(o.x - m) + expf(o.y - m) + expf(o.z - m) + expf(o.w - m);
    s += __shfl_xor_sync(gmask, s, 1, 4);
    s += __shfl_xor_sync(gmask, s, 2, 4);
    float lg = m + logf(s);

    if (nvalid) {
        float4 r;
        r.x = o.x - lg; r.y = o.y - lg; r.z = o.z - lg; r.w = o.w - lg;
        *(float4*)(out + (size_t)node * NC + sub * 4) = r;
    }
}

extern "C" void kernel_launch(void* const* d_in, const int* in_sizes, int n_in,
                              void* d_out, int out_size) {
    const float* x   = (const float*)d_in[0];
    const int*   ei  = (const int*)d_in[1];     // JAX x64 disabled -> int32!
    const float* W1  = (const float*)d_in[2];
    const float* b1  = (const float*)d_in[3];
    const float* W2  = (const float*)d_in[4];
    const float* b2  = (const float*)d_in[5];
    float*       out = (float*)d_out;

    int n = in_sizes[0] / FIN;     // 100000
    int E = in_sizes[1] / 2;       // 3200000
    const int* er = ei;            // dst (row)
    const int* ec = ei + E;        // src (col)

    int tb = 256;
    int nb = (n + SCAN_B - 1) / SCAN_B;

    k_zero<<<(n + tb - 1) / tb, tb>>>(n);
    k_count<<<(E + tb - 1) / tb, tb>>>(er, E, n);
    k_scanA<<<nb, SCAN_B>>>(n);
    k_scanB<<<1, 1>>>(nb);
    k_scanC<<<(n + tb - 1) / tb, tb>>>(n);
    k_scatter<<<(E + tb - 1) / tb, tb>>>(er, ec, E, n);

    k_gemm1<<<(n + 63) / 64, 256>>>(x, W1, n);
    k_agg1<<<(n * 8 + tb - 1) / tb, tb>>>(n);
    k_gemm2<<<(n + 255) / 256, 256>>>(W2, b1, n);
    k_agg2_lsm<<<(n * 4 + tb - 1) / tb, tb>>>(b2, out, n);
}

// round 7
// speedup vs baseline: 1.1713x; 1.1713x over previous
#include <cuda_runtime.h>

#define NMAX 100000
#define EMAX 3200000
#define FIN 128
#define HID 24
#define NC  16
#define SCAN_B 1024

// Scratch (static __device__ arrays — no allocation). 16B-aligned for float4.
__device__ int   g_cnt[NMAX];
__device__ float g_dinv[NMAX];
__device__ int   g_ptr[NMAX + 1];
__device__ int   g_cur[NMAX];
__device__ int   g_off[128];
__device__ int   g_bsum[128];
__device__ int   g_csr[EMAX];
__device__ __align__(16) float g_h1[NMAX * HID];   // dinv-scaled x@W1
__device__ __align__(16) float g_a1[NMAX * HID];   // true layer-1 output
__device__ __align__(16) float g_h2[NMAX * NC];    // dinv-scaled layer-2 features

// ---- 0. zero counts -------------------------------------------------------
__global__ void k_zero(int n) {
    int i = blockIdx.x * blockDim.x + threadIdx.x;
    if (i < n) g_cnt[i] = 0;
}

// ---- 1. count edges per dst (edge_index is int32) ------------------------
__global__ void k_count(const int* __restrict__ er, int E, int n) {
    int e = blockIdx.x * blockDim.x + threadIdx.x;
    if (e < E) {
        int r = er[e];
        if ((unsigned)r < (unsigned)n) atomicAdd(&g_cnt[r], 1);
    }
}

// ---- 2a. per-block inclusive scan (shuffle-based, 2 barriers) ------------
__global__ void k_scanA(int n) {
    __shared__ int warpsum[32];
    int tid = threadIdx.x;
    int lane = tid & 31, wid = tid >> 5;
    int gi = blockIdx.x * SCAN_B + tid;
    int v = (gi < n) ? g_cnt[gi] : 0;
    int s = v;
    #pragma unroll
    for (int d = 1; d < 32; d <<= 1) {
        int t = __shfl_up_sync(0xffffffffu, s, d);
        if (lane >= d) s += t;
    }
    if (lane == 31) warpsum[wid] = s;
    __syncthreads();
    if (wid == 0) {
        int ws = warpsum[lane];
        #pragma unroll
        for (int d = 1; d < 32; d <<= 1) {
            int t = __shfl_up_sync(0xffffffffu, ws, d);
            if (lane >= d) ws += t;
        }
        warpsum[lane] = ws;
    }
    __syncthreads();
    if (wid > 0) s += warpsum[wid - 1];
    if (gi < n) g_ptr[gi + 1] = s;
    if (tid == SCAN_B - 1) g_bsum[blockIdx.x] = s;
}

// ---- 2b. scan block totals (<=98) with one 128-thread block --------------
__global__ void k_scanB(int nb) {
    __shared__ int ws[4];
    int tid = threadIdx.x;
    int lane = tid & 31, wid = tid >> 5;
    int v = (tid < nb) ? g_bsum[tid] : 0;
    int s = v;
    #pragma unroll
    for (int d = 1; d < 32; d <<= 1) {
        int t = __shfl_up_sync(0xffffffffu, s, d);
        if (lane >= d) s += t;
    }
    if (lane == 31) ws[wid] = s;
    __syncthreads();
    int add = 0;
    #pragma unroll
    for (int w = 0; w < 4; w++) if (w < wid) add += ws[w];
    if (tid < nb) g_off[tid] = s + add - v;   // exclusive prefix
}

// ---- 2c. add offsets; cursors + dinv -------------------------------------
__global__ void k_scanC(int n) {
    int i = blockIdx.x * blockDim.x + threadIdx.x;
    if (i >= n) return;
    int off = g_off[i / SCAN_B];
    int inc = g_ptr[i + 1] + off;
    g_ptr[i + 1] = inc;
    g_cur[i] = inc - g_cnt[i];
    g_dinv[i] = rsqrtf((float)g_cnt[i] + 1.0f);
    if (i == 0) g_ptr[0] = 0;
}

// ---- 3. scatter cols into CSR --------------------------------------------
__global__ void k_scatter(const int* __restrict__ er,
                          const int* __restrict__ ec, int E, int n) {
    int e = blockIdx.x * blockDim.x + threadIdx.x;
    if (e >= E) return;
    int r = er[e];
    int c = ec[e];
    if ((unsigned)r < (unsigned)n && (unsigned)c < (unsigned)n) {
        int pos = atomicAdd(&g_cur[r], 1);
        g_csr[pos] = c;
    }
}

// ---- 4. GEMM1: g_h1 = dinv * (x @ W1) ------------------------------------
__global__ void k_gemm1(const float* __restrict__ x, const float* __restrict__ W1, int n) {
    __shared__ float sx[64 * 129];
    __shared__ float sw[FIN * HID];
    int tid = threadIdx.x;
    int rowBase = blockIdx.x * 64;

    for (int i = tid; i < FIN * HID; i += 256) sw[i] = W1[i];
    // x tile as float4: 64 rows x 32 float4
    for (int i = tid; i < 64 * 32; i += 256) {
        int r = i >> 5, q = i & 31;
        int gr = rowBase + r;
        float4 v = make_float4(0.f, 0.f, 0.f, 0.f);
        if (gr < n) v = *(const float4*)(x + (size_t)gr * FIN + q * 4);
        float* dst = sx + r * 129 + q * 4;
        dst[0] = v.x; dst[1] = v.y; dst[2] = v.z; dst[3] = v.w;
    }
    __syncthreads();

    int r   = tid & 63;
    int grp = tid >> 6;
    int j0  = grp * 6;
    float acc[6] = {0.f, 0.f, 0.f, 0.f, 0.f, 0.f};
    #pragma unroll 4
    for (int k = 0; k < FIN; k++) {
        float xv = sx[r * 129 + k];
        #pragma unroll
        for (int c = 0; c < 6; c++) acc[c] += xv * sw[k * HID + j0 + c];
    }
    __syncthreads();

    float* so = sx;  // reuse: 64 x 25
    #pragma unroll
    for (int c = 0; c < 6; c++) so[r * 25 + j0 + c] = acc[c];
    __syncthreads();

    for (int i = tid; i < 64 * HID; i += 256) {
        int rr = i / HID, j = i - rr * HID;
        int gr = rowBase + rr;
        if (gr < n) g_h1[(size_t)gr * HID + j] = so[rr * 25 + j] * g_dinv[gr];
    }
}

// ---- 5. Aggregation layer 1: a1[r] = dinv[r]*(h1'[r] + sum h1'[c]) -------
// 8 threads/node, 6 active float4 lanes; index-only shuffles.
__global__ void k_agg1(int n) {
    int t = blockIdx.x * blockDim.x + threadIdx.x;
    int node = t >> 3;
    bool nvalid = node < n;
    int nc = nvalid ? node : 0;
    int lane = threadIdx.x & 31;
    unsigned gmask = 0xffu << (lane & ~7);
    int sub = t & 7;
    bool active = nvalid && sub < 6;

    int start = nvalid ? g_ptr[nc]     : 0;
    int end   = nvalid ? g_ptr[nc + 1] : 0;
    float dr  = g_dinv[nc];

    float4 acc = make_float4(0.f, 0.f, 0.f, 0.f);
    if (active) acc = *(const float4*)(g_h1 + (size_t)nc * HID + sub * 4);

    for (int j0 = start; j0 < end; j0 += 8) {
        int jj = j0 + sub;
        int cc = (jj < end) ? __ldg(g_csr + jj) : -1;
        #pragma unroll
        for (int k = 0; k < 8; k++) {
            int ck = __shfl_sync(gmask, cc, k, 8);
            if (ck >= 0 && active) {
                float4 v = *(const float4*)(g_h1 + (size_t)ck * HID + sub * 4);
                acc.x += v.x; acc.y += v.y; acc.z += v.z; acc.w += v.w;
            }
        }
    }
    if (active) {
        float4 o = make_float4(dr * acc.x, dr * acc.y, dr * acc.z, dr * acc.w);
        *(float4*)(g_a1 + (size_t)nc * HID + sub * 4) = o;
    }
}

// ---- 6. GEMM2: g_h2 = dinv * (relu(a1 + b1) @ W2) ------------------------
__global__ void k_gemm2(const float* __restrict__ W2, const float* __restrict__ b1, int n) {
    __shared__ float sa[256 * 25];
    __shared__ float sw[HID * NC];
    int tid = threadIdx.x;
    int rowBase = blockIdx.x * 256;

    for (int i = tid; i < HID * NC; i += 256) sw[i] = W2[i];
    for (int i = tid; i < 256 * HID; i += 256) {
        int r = i / HID, k = i - r * HID;
        int gr = rowBase + r;
        float v = (gr < n) ? g_a1[(size_t)gr * HID + k] : 0.0f;
        sa[r * 25 + k] = fmaxf(v + b1[k], 0.0f);
    }
    __syncthreads();

    int r = tid;
    float acc[NC];
    #pragma unroll
    for (int j = 0; j < NC; j++) acc[j] = 0.0f;
    #pragma unroll
    for (int k = 0; k < HID; k++) {
        float xv = sa[r * 25 + k];
        #pragma unroll
        for (int j = 0; j < NC; j++) acc[j] += xv * sw[k * NC + j];
    }
    __syncthreads();

    float* so = sa;  // reuse: 256 x 17
    #pragma unroll
    for (int j = 0; j < NC; j++) so[r * 17 + j] = acc[j];
    __syncthreads();

    for (int i = tid; i < 256 * NC; i += 256) {
        int rr = i >> 4, j = i & 15;
        int gr = rowBase + rr;
        if (gr < n) g_h2[(size_t)gr * NC + j] = so[rr * 17 + j] * g_dinv[gr];
    }
}

// ---- 7. Aggregation layer 2 + bias + log_softmax fused -------------------
__global__ void k_agg2_lsm(const float* __restrict__ b2, float* __restrict__ out, int n) {
    int t = blockIdx.x * blockDim.x + threadIdx.x;
    int node = t >> 2;
    bool nvalid = node < n;
    int ncl = nvalid ? node : 0;
    int lane = threadIdx.x & 31;
    unsigned gmask = 0xfu << (lane & ~3);
    int sub = t & 3;

    int start = nvalid ? g_ptr[ncl]     : 0;
    int end   = nvalid ? g_ptr[ncl + 1] : 0;
    float dr  = g_dinv[ncl];

    float4 acc = *(const float4*)(g_h2 + (size_t)ncl * NC + sub * 4);

    for (int j0 = start; j0 < end; j0 += 4) {
        int jj = j0 + sub;
        int cc = (jj < end) ? __ldg(g_csr + jj) : -1;
        #pragma unroll
        for (int k = 0; k < 4; k++) {
            int ck = __shfl_sync(gmask, cc, k, 4);
            if (ck >= 0) {
                float4 v = *(const float4*)(g_h2 + (size_t)ck * NC + sub * 4);
                acc.x += v.x; acc.y += v.y; acc.z += v.z; acc.w += v.w;
            }
        }
    }

    float4 bb = *(const float4*)(b2 + sub * 4);
    float4 o;
    o.x = dr * acc.x + bb.x; o.y = dr * acc.y + bb.y;
    o.z = dr * acc.z + bb.z; o.w = dr * acc.w + bb.w;

    float m = fmaxf(fmaxf(o.x, o.y), fmaxf(o.z, o.w));
    m = fmaxf(m, __shfl_xor_sync(gmask, m, 1, 4));
    m = fmaxf(m, __shfl_xor_sync(gmask, m, 2, 4));
    float s = expf(o.x - m) + expf(o.y - m) + expf(o.z - m) + expf(o.w - m);
    s += __shfl_xor_sync(gmask, s, 1, 4);
    s += __shfl_xor_sync(gmask, s, 2, 4);
    float lg = m + logf(s);

    if (nvalid) {
        float4 r;
        r.x = o.x - lg; r.y = o.y - lg; r.z = o.z - lg; r.w = o.w - lg;
        *(float4*)(out + (size_t)node * NC + sub * 4) = r;
    }
}

extern "C" void kernel_launch(void* const* d_in, const int* in_sizes, int n_in,
                              void* d_out, int out_size) {
    const float* x   = (const float*)d_in[0];
    const int*   ei  = (const int*)d_in[1];     // int32 (JAX x64 disabled)
    const float* W1  = (const float*)d_in[2];
    const float* b1  = (const float*)d_in[3];
    const float* W2  = (const float*)d_in[4];
    const float* b2  = (const float*)d_in[5];
    float*       out = (float*)d_out;

    int n = in_sizes[0] / FIN;     // 100000
    int E = in_sizes[1] / 2;       // 3200000
    const int* er = ei;            // dst (row)
    const int* ec = ei + E;        // src (col)

    int tb = 256;
    int nb = (n + SCAN_B - 1) / SCAN_B;

    k_zero<<<(n + tb - 1) / tb, tb>>>(n);
    k_count<<<(E + tb - 1) / tb, tb>>>(er, E, n);
    k_scanA<<<nb, SCAN_B>>>(n);
    k_scanB<<<1, 128>>>(nb);
    k_scanC<<<(n + tb - 1) / tb, tb>>>(n);
    k_scatter<<<(E + tb - 1) / tb, tb>>>(er, ec, E, n);

    k_gemm1<<<(n + 63) / 64, 256>>>(x, W1, n);
    k_agg1<<<(n * 8 + tb - 1) / tb, tb>>>(n);
    k_gemm2<<<(n + 255) / 256, 256>>>(W2, b1, n);
    k_agg2_lsm<<<(n * 4 + tb - 1) / tb, tb>>>(b2, out, n);
}

// round 8
// speedup vs baseline: 1.1849x; 1.0116x over previous
#include <cuda_runtime.h>

#define NMAX 100000
#define EMAX 3200000
#define FIN 128
#define HID 24
#define NC  16
#define SCAN_B 1024

// Scratch (static __device__ arrays — no allocation). 16B-aligned for float4.
__device__ int   g_cnt[NMAX];
__device__ float g_dinv[NMAX];
__device__ int   g_ptr[NMAX + 1];
__device__ int   g_cur[NMAX];
__device__ int   g_bsum[128];
__device__ int   g_csr[EMAX];
__device__ __align__(16) float g_h1[NMAX * HID];   // dinv-scaled x@W1
__device__ __align__(16) float g_a1[NMAX * HID];   // true layer-1 output
__device__ __align__(16) float g_h2[NMAX * NC];    // dinv-scaled layer-2 features

// ---- packed f32x2 helpers -------------------------------------------------
__device__ __forceinline__ unsigned long long pk2(float a, float b) {
    unsigned long long r;
    asm("mov.b64 %0, {%1,%2};" : "=l"(r) : "f"(a), "f"(b));
    return r;
}
__device__ __forceinline__ void fma2(unsigned long long& acc,
                                     unsigned long long a, unsigned long long b) {
    asm("fma.rn.f32x2 %0, %1, %2, %0;" : "+l"(acc) : "l"(a), "l"(b));
}
__device__ __forceinline__ float upk_sum(unsigned long long v) {
    float lo, hi;
    asm("mov.b64 {%0,%1}, %2;" : "=f"(lo), "=f"(hi) : "l"(v));
    return lo + hi;
}

// ---- 0. zero counts -------------------------------------------------------
__global__ void k_zero(int n) {
    int i = blockIdx.x * blockDim.x + threadIdx.x;
    if (i < n) g_cnt[i] = 0;
}

// ---- 1. count edges per dst ----------------------------------------------
__global__ void k_count(const int* __restrict__ er, int E, int n) {
    int e = blockIdx.x * blockDim.x + threadIdx.x;
    if (e < E) {
        int r = er[e];
        if ((unsigned)r < (unsigned)n) atomicAdd(&g_cnt[r], 1);
    }
}

// ---- 2a. per-block inclusive scan (shuffle-based) ------------------------
__global__ void k_scanA(int n) {
    __shared__ int warpsum[32];
    int tid = threadIdx.x;
    int lane = tid & 31, wid = tid >> 5;
    int gi = blockIdx.x * SCAN_B + tid;
    int v = (gi < n) ? g_cnt[gi] : 0;
    int s = v;
    #pragma unroll
    for (int d = 1; d < 32; d <<= 1) {
        int t = __shfl_up_sync(0xffffffffu, s, d);
        if (lane >= d) s += t;
    }
    if (lane == 31) warpsum[wid] = s;
    __syncthreads();
    if (wid == 0) {
        int ws = warpsum[lane];
        #pragma unroll
        for (int d = 1; d < 32; d <<= 1) {
            int t = __shfl_up_sync(0xffffffffu, ws, d);
            if (lane >= d) ws += t;
        }
        warpsum[lane] = ws;
    }
    __syncthreads();
    if (wid > 0) s += warpsum[wid - 1];
    if (gi < n) g_ptr[gi + 1] = s;
    if (tid == SCAN_B - 1) g_bsum[blockIdx.x] = s;
}

// ---- 2b. add offsets (self-computed); cursors + dinv ---------------------
// Each 256-node block lies inside one 1024-node scanA block -> one offset.
__global__ void k_scanC(int n) {
    __shared__ int soff;
    int tid = threadIdx.x;
    int B = blockIdx.x >> 2;                 // scanA block index
    if (tid < 32) {
        int part = 0;
        for (int j = tid; j < B; j += 32) part += g_bsum[j];
        #pragma unroll
        for (int d = 16; d; d >>= 1) part += __shfl_xor_sync(0xffffffffu, part, d);
        if (tid == 0) soff = part;
    }
    __syncthreads();
    int i = blockIdx.x * 256 + tid;
    if (i >= n) return;
    int inc = g_ptr[i + 1] + soff;
    g_ptr[i + 1] = inc;
    g_cur[i] = inc - g_cnt[i];
    g_dinv[i] = rsqrtf((float)g_cnt[i] + 1.0f);
    if (i == 0) g_ptr[0] = 0;
}

// ---- 3. scatter cols into CSR --------------------------------------------
__global__ void k_scatter(const int* __restrict__ er,
                          const int* __restrict__ ec, int E, int n) {
    int e = blockIdx.x * blockDim.x + threadIdx.x;
    if (e >= E) return;
    int r = er[e];
    int c = ec[e];
    if ((unsigned)r < (unsigned)n && (unsigned)c < (unsigned)n) {
        int pos = atomicAdd(&g_cur[r], 1);
        g_csr[pos] = c;
    }
}

// ---- 4. GEMM1: g_h1 = dinv * (x @ W1), packed f32x2 ----------------------
// 256 threads, 64 rows/block, 4 col-groups of 6. W transposed in smem.
__global__ void k_gemm1(const float* __restrict__ x, const float* __restrict__ W1, int n) {
    __shared__ __align__(16) float sx[64 * 132];    // stride 132: float4-aligned, conflict-free
    __shared__ __align__(16) float swt[HID * 132];  // swt[j*132+k] = W1[k*24+j]
    int tid = threadIdx.x;
    int rowBase = blockIdx.x * 64;

    // x tile as float4
    for (int i = tid; i < 64 * 32; i += 256) {
        int r = i >> 5, q = i & 31;
        int gr = rowBase + r;
        float4 v = make_float4(0.f, 0.f, 0.f, 0.f);
        if (gr < n) v = *(const float4*)(x + (size_t)gr * FIN + q * 4);
        *(float4*)(sx + r * 132 + q * 4) = v;
    }
    // W transposed: read W1 as float4 rows (coalesced), scatter into swt
    for (int i = tid; i < FIN * (HID / 4); i += 256) {
        int k = i / (HID / 4), jq = i - k * (HID / 4);
        float4 w = *(const float4*)(W1 + k * HID + jq * 4);
        swt[(jq * 4 + 0) * 132 + k] = w.x;
        swt[(jq * 4 + 1) * 132 + k] = w.y;
        swt[(jq * 4 + 2) * 132 + k] = w.z;
        swt[(jq * 4 + 3) * 132 + k] = w.w;
    }
    __syncthreads();

    int r   = tid & 63;
    int grp = tid >> 6;
    int j0  = grp * 6;
    unsigned long long acc[6];
    #pragma unroll
    for (int c = 0; c < 6; c++) acc[c] = 0ull;

    const float* xrow = sx + r * 132;
    #pragma unroll 4
    for (int k = 0; k < FIN; k += 4) {
        float4 xv = *(const float4*)(xrow + k);
        unsigned long long xlo = pk2(xv.x, xv.y);
        unsigned long long xhi = pk2(xv.z, xv.w);
        #pragma unroll
        for (int c = 0; c < 6; c++) {
            float4 wv = *(const float4*)(swt + (j0 + c) * 132 + k);
            fma2(acc[c], xlo, pk2(wv.x, wv.y));
            fma2(acc[c], xhi, pk2(wv.z, wv.w));
        }
    }
    __syncthreads();

    float* so = sx;  // reuse: 64 x 25
    #pragma unroll
    for (int c = 0; c < 6; c++) so[r * 25 + j0 + c] = upk_sum(acc[c]);
    __syncthreads();

    for (int i = tid; i < 64 * HID; i += 256) {
        int rr = i / HID, j = i - rr * HID;
        int gr = rowBase + rr;
        if (gr < n) g_h1[(size_t)gr * HID + j] = so[rr * 25 + j] * g_dinv[gr];
    }
}

// ---- 5. Aggregation layer 1: a1[r] = dinv[r]*(h1'[r] + sum h1'[c]) -------
__global__ void k_agg1(int n) {
    int t = blockIdx.x * blockDim.x + threadIdx.x;
    int node = t >> 3;
    bool nvalid = node < n;
    int nc = nvalid ? node : 0;
    int lane = threadIdx.x & 31;
    unsigned gmask = 0xffu << (lane & ~7);
    int sub = t & 7;
    bool active = nvalid && sub < 6;

    int start = nvalid ? g_ptr[nc]     : 0;
    int end   = nvalid ? g_ptr[nc + 1] : 0;
    float dr  = g_dinv[nc];

    float4 acc = make_float4(0.f, 0.f, 0.f, 0.f);
    if (active) acc = *(const float4*)(g_h1 + (size_t)nc * HID + sub * 4);

    int nfull = start + ((end - start) & ~7);
    int j0 = start;
    for (; j0 < nfull; j0 += 8) {                  // branch-free main chunks
        int cc = __ldg(g_csr + j0 + sub);
        #pragma unroll
        for (int k = 0; k < 8; k++) {
            int ck = __shfl_sync(gmask, cc, k, 8);
            if (active) {
                float4 v = *(const float4*)(g_h1 + (size_t)ck * HID + sub * 4);
                acc.x += v.x; acc.y += v.y; acc.z += v.z; acc.w += v.w;
            }
        }
    }
    if (j0 < end) {                                // guarded remainder (<8)
        int jj = j0 + sub;
        int cc = (jj < end) ? __ldg(g_csr + jj) : -1;
        #pragma unroll
        for (int k = 0; k < 8; k++) {
            int ck = __shfl_sync(gmask, cc, k, 8);
            if (ck >= 0 && active) {
                float4 v = *(const float4*)(g_h1 + (size_t)ck * HID + sub * 4);
                acc.x += v.x; acc.y += v.y; acc.z += v.z; acc.w += v.w;
            }
        }
    }
    if (active) {
        float4 o = make_float4(dr * acc.x, dr * acc.y, dr * acc.z, dr * acc.w);
        *(float4*)(g_a1 + (size_t)nc * HID + sub * 4) = o;
    }
}

// ---- 6. GEMM2: g_h2 = dinv * (relu(a1 + b1) @ W2) ------------------------
__global__ void k_gemm2(const float* __restrict__ W2, const float* __restrict__ b1, int n) {
    __shared__ float sa[256 * 25];
    __shared__ float sw[HID * NC];
    int tid = threadIdx.x;
    int rowBase = blockIdx.x * 256;

    for (int i = tid; i < HID * NC; i += 256) sw[i] = W2[i];
    for (int i = tid; i < 256 * HID; i += 256) {
        int r = i / HID, k = i - r * HID;
        int gr = rowBase + r;
        float v = (gr < n) ? g_a1[(size_t)gr * HID + k] : 0.0f;
        sa[r * 25 + k] = fmaxf(v + b1[k], 0.0f);
    }
    __syncthreads();

    int r = tid;
    float acc[NC];
    #pragma unroll
    for (int j = 0; j < NC; j++) acc[j] = 0.0f;
    #pragma unroll
    for (int k = 0; k < HID; k++) {
        float xv = sa[r * 25 + k];
        #pragma unroll
        for (int j = 0; j < NC; j++) acc[j] += xv * sw[k * NC + j];
    }
    __syncthreads();

    float* so = sa;  // reuse: 256 x 17
    #pragma unroll
    for (int j = 0; j < NC; j++) so[r * 17 + j] = acc[j];
    __syncthreads();

    for (int i = tid; i < 256 * NC; i += 256) {
        int rr = i >> 4, j = i & 15;
        int gr = rowBase + rr;
        if (gr < n) g_h2[(size_t)gr * NC + j] = so[rr * 17 + j] * g_dinv[gr];
    }
}

// ---- 7. Aggregation layer 2 + bias + log_softmax fused -------------------
__global__ void k_agg2_lsm(const float* __restrict__ b2, float* __restrict__ out, int n) {
    int t = blockIdx.x * blockDim.x + threadIdx.x;
    int node = t >> 2;
    bool nvalid = node < n;
    int ncl = nvalid ? node : 0;
    int lane = threadIdx.x & 31;
    unsigned gmask = 0xfu << (lane & ~3);
    int sub = t & 3;

    int start = nvalid ? g_ptr[ncl]     : 0;
    int end   = nvalid ? g_ptr[ncl + 1] : 0;
    float dr  = g_dinv[ncl];

    float4 acc = *(const float4*)(g_h2 + (size_t)ncl * NC + sub * 4);

    int nfull = start + ((end - start) & ~3);
    int j0 = start;
    for (; j0 < nfull; j0 += 4) {                  // branch-free main chunks
        int cc = __ldg(g_csr + j0 + sub);
        #pragma unroll
        for (int k = 0; k < 4; k++) {
            int ck = __shfl_sync(gmask, cc, k, 4);
            float4 v = *(const float4*)(g_h2 + (size_t)ck * NC + sub * 4);
            acc.x += v.x; acc.y += v.y; acc.z += v.z; acc.w += v.w;
        }
    }
    if (j0 < end) {                                // guarded remainder (<4)
        int jj = j0 + sub;
        int cc = (jj < end) ? __ldg(g_csr + jj) : -1;
        #pragma unroll
        for (int k = 0; k < 4; k++) {
            int ck = __shfl_sync(gmask, cc, k, 4);
            if (ck >= 0) {
                float4 v = *(const float4*)(g_h2 + (size_t)ck * NC + sub * 4);
                acc.x += v.x; acc.y += v.y; acc.z += v.z; acc.w += v.w;
            }
        }
    }

    float4 bb = *(const float4*)(b2 + sub * 4);
    float4 o;
    o.x = dr * acc.x + bb.x; o.y = dr * acc.y + bb.y;
    o.z = dr * acc.z + bb.z; o.w = dr * acc.w + bb.w;

    float m = fmaxf(fmaxf(o.x, o.y), fmaxf(o.z, o.w));
    m = fmaxf(m, __shfl_xor_sync(gmask, m, 1, 4));
    m = fmaxf(m, __shfl_xor_sync(gmask, m, 2, 4));
    float s = expf(o.x - m) + expf(o.y - m) + expf(o.z - m) + expf(o.w - m);
    s += __shfl_xor_sync(gmask, s, 1, 4);
    s += __shfl_xor_sync(gmask, s, 2, 4);
    float lg = m + logf(s);

    if (nvalid) {
        float4 r;
        r.x = o.x - lg; r.y = o.y - lg; r.z = o.z - lg; r.w = o.w - lg;
        *(float4*)(out + (size_t)node * NC + sub * 4) = r;
    }
}

extern "C" void kernel_launch(void* const* d_in, const int* in_sizes, int n_in,
                              void* d_out, int out_size) {
    const float* x   = (const float*)d_in[0];
    const int*   ei  = (const int*)d_in[1];     // int32 (JAX x64 disabled)
    const float* W1  = (const float*)d_in[2];
    const float* b1  = (const float*)d_in[3];
    const float* W2  = (const float*)d_in[4];
    const float* b2  = (const float*)d_in[5];
    float*       out = (float*)d_out;

    int n = in_sizes[0] / FIN;     // 100000
    int E = in_sizes[1] / 2;       // 3200000
    const int* er = ei;            // dst (row)
    const int* ec = ei + E;        // src (col)

    int tb = 256;
    int nb = (n + SCAN_B - 1) / SCAN_B;

    k_zero<<<(n + tb - 1) / tb, tb>>>(n);
    k_count<<<(E + tb - 1) / tb, tb>>>(er, E, n);
    k_scanA<<<nb, SCAN_B>>>(n);
    k_scanC<<<(n + 255) / 256, 256>>>(n);
    k_scatter<<<(E + tb - 1) / tb, tb>>>(er, ec, E, n);

    k_gemm1<<<(n + 63) / 64, 256>>>(x, W1, n);
    k_agg1<<<(n * 8 + tb - 1) / tb, tb>>>(n);
    k_gemm2<<<(n + 255) / 256, 256>>>(W2, b1, n);
    k_agg2_lsm<<<(n * 4 + tb - 1) / tb, tb>>>(b2, out, n);
}